// round 1
// baseline (speedup 1.0000x reference)
#include <cuda_runtime.h>
#include <cuda_bf16.h>
#include <math.h>

#define NN 100000
#define EE 1600000
#define EPSV 1e-16f
#define NEG_SLOPE 0.2f

// ---------------- scratch (device globals; allocation-free) ----------------
__device__ float4 g_h1[NN * 32];       // h1 [N,128]           51.2 MB
__device__ float4 g_as1[NN * 2];       // alpha_src1 [N,8]      3.2 MB
__device__ float4 g_ad1[NN * 2];       // alpha_dst1 [N,8]      3.2 MB
__device__ float4 g_ebuf[EE * 2];      // exp(e) per edge [E,8] 51.2 MB
__device__ float4 g_d1[NN * 2];        // denom1 [N,8]          3.2 MB
__device__ float4 g_out1[NN * 32];     // out1 / elu-h [N,128]  51.2 MB
__device__ float4 g_g2[NN * 10];       // g2 [N,40]             16 MB
__device__ float4 g_as2[NN / 4];       // alpha_src2 [N]
__device__ float4 g_ad2[NN / 4];       // alpha_dst2 [N]
__device__ float4 g_e2[EE / 4];        // exp(e2) [E]           6.4 MB
__device__ float4 g_d2[NN / 4];        // denom2 [N]
__device__ float4 g_out2[NN * 10];     // out2 accum [N,40]     16 MB

// ---------------- helpers ----------------
__device__ __forceinline__ void fma4(float4& a, float s, float4 b) {
    a.x += s * b.x; a.y += s * b.y; a.z += s * b.z; a.w += s * b.w;
}
__device__ __forceinline__ float dot4(float4 a, float4 b) {
    return a.x * b.x + a.y * b.y + a.z * b.z + a.w * b.w;
}
__device__ __forceinline__ float4 add4(float4 a, float4 b) {
    return make_float4(a.x + b.x, a.y + b.y, a.z + b.z, a.w + b.w);
}
__device__ __forceinline__ float4 scale4(float4 a, float s) {
    return make_float4(a.x * s, a.y * s, a.z * s, a.w * s);
}
// vector global reduction (sm_90+): one RED.128 instead of 4 scalar REDs
__device__ __forceinline__ void red4(float* p, float4 v) {
    asm volatile("red.global.add.v4.f32 [%0], {%1,%2,%3,%4};"
                 :: "l"(p), "f"(v.x), "f"(v.y), "f"(v.z), "f"(v.w) : "memory");
}
__device__ __forceinline__ float leaky_exp(float e) {
    float t = e > 0.f ? e : NEG_SLOPE * e;
    return __expf(t);
}

// ---------------- 0. zero accumulators ----------------
__global__ __launch_bounds__(256) void zero_kernel() {
    int i = blockIdx.x * 256 + threadIdx.x;   // grid covers 3.2M
    float4 z = make_float4(0.f, 0.f, 0.f, 0.f);
    if (i < NN * 32) g_out1[i] = z;
    if (i < NN * 10) g_out2[i] = z;
    if (i < NN * 2)  g_d1[i]  = z;
    if (i < NN / 4)  g_d2[i]  = z;
}

// ---------------- 1. GEMM1: h1 = x@W1 [128->128], + per-head alphas ----------
// 32 nodes/block, 256 threads: thread = (node_local = tid/8, head cg = tid%8),
// each thread owns head cg's 16 output channels (4 x float4).
__global__ __launch_bounds__(256) void gemm1_kernel(
    const float* __restrict__ x, const float* __restrict__ W1,
    const float* __restrict__ a_src, const float* __restrict__ a_dst)
{
    __shared__ float4 sW[64 * 32];     // 64 k-rows x 128 cols (32 f4) = 32 KB
    __shared__ float  sx[32 * 65];     // 32 nodes x 64 k, padded     ~8.3 KB
    const int tid = threadIdx.x;
    const int nl = tid >> 3, cg = tid & 7;
    const int nbase = blockIdx.x * 32;
    const float4* W4 = (const float4*)W1;

    float4 a0 = make_float4(0, 0, 0, 0), a1 = a0, a2 = a0, a3 = a0;

    for (int k0 = 0; k0 < 128; k0 += 64) {
        #pragma unroll
        for (int it = 0; it < 8; it++) {            // W half: 2048 f4
            int f = tid + it * 256;
            sW[f] = W4[(k0 + (f >> 5)) * 32 + (f & 31)];
        }
        #pragma unroll
        for (int it = 0; it < 8; it++) {            // x half: 2048 floats
            int f = tid + it * 256;
            int n = f >> 6, k = f & 63;
            sx[n * 65 + k] = x[(nbase + n) * 128 + k0 + k];
        }
        __syncthreads();
        #pragma unroll 8
        for (int r = 0; r < 64; r++) {
            float xv = sx[nl * 65 + r];
            const float4* wr = &sW[r * 32 + cg * 4];
            fma4(a0, xv, wr[0]); fma4(a1, xv, wr[1]);
            fma4(a2, xv, wr[2]); fma4(a3, xv, wr[3]);
        }
        __syncthreads();
    }

    const int node = nbase + nl;
    const float4* as4 = (const float4*)a_src;   // [8,16] = 32 f4
    const float4* ad4 = (const float4*)a_dst;
    float ssrc = dot4(a0, as4[cg * 4 + 0]) + dot4(a1, as4[cg * 4 + 1])
               + dot4(a2, as4[cg * 4 + 2]) + dot4(a3, as4[cg * 4 + 3]);
    float sdst = dot4(a0, ad4[cg * 4 + 0]) + dot4(a1, ad4[cg * 4 + 1])
               + dot4(a2, ad4[cg * 4 + 2]) + dot4(a3, ad4[cg * 4 + 3]);
    g_h1[node * 32 + cg * 4 + 0] = a0;
    g_h1[node * 32 + cg * 4 + 1] = a1;
    g_h1[node * 32 + cg * 4 + 2] = a2;
    g_h1[node * 32 + cg * 4 + 3] = a3;
    ((float*)g_as1)[node * 8 + cg] = ssrc;
    ((float*)g_ad1)[node * 8 + cg] = sdst;
}

// ---------------- 2. L1 edge pass 1: ex = exp(leaky(a_s[src]+a_d[dst])),
//                    store ex, accumulate denom[dst] -------------------------
__global__ __launch_bounds__(256) void edge1_l1(
    const int* __restrict__ src, const int* __restrict__ dst)
{
    int i = blockIdx.x * 256 + threadIdx.x;
    if (i >= EE) return;
    int s = __ldcs(src + i), d = __ldcs(dst + i);
    float4 e0 = add4(g_as1[s * 2 + 0], g_ad1[d * 2 + 0]);
    float4 e1 = add4(g_as1[s * 2 + 1], g_ad1[d * 2 + 1]);
    float4 x0 = make_float4(leaky_exp(e0.x), leaky_exp(e0.y), leaky_exp(e0.z), leaky_exp(e0.w));
    float4 x1 = make_float4(leaky_exp(e1.x), leaky_exp(e1.y), leaky_exp(e1.z), leaky_exp(e1.w));
    __stcs(&g_ebuf[i * 2 + 0], x0);
    __stcs(&g_ebuf[i * 2 + 1], x1);
    red4((float*)&g_d1[d * 2 + 0], x0);
    red4((float*)&g_d1[d * 2 + 1], x1);
}

// ---------------- 3. L1 aggregate: out1[dst] += h1[src]*alpha (warp/edge) ----
__global__ __launch_bounds__(256) void edge2_l1(
    const int* __restrict__ src, const int* __restrict__ dst)
{
    int w = (blockIdx.x * 256 + threadIdx.x) >> 5;   // edge id
    int l = threadIdx.x & 31;
    int s = __ldcs(src + w), d = __ldcs(dst + w);
    float a8 = 0.f;
    if (l < 8) {
        float ex = __ldcs(((const float*)g_ebuf) + (size_t)w * 8 + l);
        float dv = ((const float*)g_d1)[d * 8 + l];
        a8 = ex / (dv + EPSV);
    }
    float alpha = __shfl_sync(0xffffffffu, a8, l >> 2);   // head = l/4
    float4 h = g_h1[s * 32 + l];
    red4((float*)&g_out1[d * 32 + l], scale4(h, alpha));
}

// ---------------- 4. finalize L1: out1 = elu(out1 + b1) (in place) ----------
__global__ __launch_bounds__(256) void fin1_kernel(const float* __restrict__ b1) {
    int f = blockIdx.x * 256 + threadIdx.x;          // N*32 f4
    float4 v = add4(g_out1[f], ((const float4*)b1)[f & 31]);
    v.x = v.x > 0.f ? v.x : __expf(v.x) - 1.f;
    v.y = v.y > 0.f ? v.y : __expf(v.y) - 1.f;
    v.z = v.z > 0.f ? v.z : __expf(v.z) - 1.f;
    v.w = v.w > 0.f ? v.w : __expf(v.w) - 1.f;
    g_out1[f] = v;
}

// ---------------- 5. GEMM2: g2 = elu_h @ W2 [128->40], scalar alphas --------
// 256 nodes/block, 1 node/thread, 10 float4 accumulators, x staged in smem.
__global__ __launch_bounds__(256) void gemm2_kernel(
    const float* __restrict__ W2, const float* __restrict__ a_src,
    const float* __restrict__ a_dst)
{
    __shared__ float4 sW[128 * 10];     // 20 KB
    __shared__ float4 sas[10], sad[10];
    __shared__ float  sx[256 * 17];     // 17.4 KB, pad 17 -> conflict-free
    const int tid = threadIdx.x;
    const int node = blockIdx.x * 256 + tid;
    const float4* W4 = (const float4*)W2;
    #pragma unroll
    for (int it = 0; it < 5; it++) sW[tid + it * 256] = W4[tid + it * 256];
    if (tid < 10) { sas[tid] = ((const float4*)a_src)[tid];
                    sad[tid] = ((const float4*)a_dst)[tid]; }
    const float* hin = (const float*)g_out1;

    float4 acc[10];
    #pragma unroll
    for (int j = 0; j < 10; j++) acc[j] = make_float4(0, 0, 0, 0);

    for (int kc = 0; kc < 8; kc++) {
        __syncthreads();
        #pragma unroll
        for (int it = 0; it < 16; it++) {            // 256 nodes x 16 k
            int f = tid + it * 256;
            int n = f >> 4, k = f & 15;
            int gn = blockIdx.x * 256 + n;
            sx[n * 17 + k] = (gn < NN) ? hin[(size_t)gn * 128 + kc * 16 + k] : 0.f;
        }
        __syncthreads();
        #pragma unroll
        for (int k = 0; k < 16; k++) {
            float xv = sx[tid * 17 + k];
            const float4* wr = &sW[(kc * 16 + k) * 10];
            #pragma unroll
            for (int j = 0; j < 10; j++) fma4(acc[j], xv, wr[j]);
        }
    }
    if (node < NN) {
        float s = 0.f, d = 0.f;
        #pragma unroll
        for (int j = 0; j < 10; j++) { s += dot4(acc[j], sas[j]); d += dot4(acc[j], sad[j]); }
        #pragma unroll
        for (int j = 0; j < 10; j++) g_g2[node * 10 + j] = acc[j];
        ((float*)g_as2)[node] = s;
        ((float*)g_ad2)[node] = d;
    }
}

// ---------------- 6. L2 edge pass 1 ----------------
__global__ __launch_bounds__(256) void edge1_l2(
    const int* __restrict__ src, const int* __restrict__ dst)
{
    int i = blockIdx.x * 256 + threadIdx.x;
    if (i >= EE) return;
    int s = __ldcs(src + i), d = __ldcs(dst + i);
    float e = ((const float*)g_as2)[s] + ((const float*)g_ad2)[d];
    float ex = leaky_exp(e);
    __stcs(((float*)g_e2) + i, ex);
    atomicAdd(((float*)g_d2) + d, ex);
}

// ---------------- 7. L2 aggregate: out2[dst] += g2[src]*alpha ---------------
__global__ __launch_bounds__(256) void edge2_l2(
    const int* __restrict__ src, const int* __restrict__ dst)
{
    int t = blockIdx.x * 256 + threadIdx.x;          // E*10 threads
    int e = t / 10;
    int j = t - e * 10;
    int s = __ldcs(src + e), d = __ldcs(dst + e);
    float alpha = __ldcs(((const float*)g_e2) + e) / (((const float*)g_d2)[d] + EPSV);
    float4 g = g_g2[s * 10 + j];
    red4((float*)&g_out2[d * 10 + j], scale4(g, alpha));
}

// ---------------- 8. finalize: +b2 then log_softmax over 40 (warp/node) -----
__global__ __launch_bounds__(256) void fin2_kernel(
    const float* __restrict__ b2, float* __restrict__ out)
{
    int w = (blockIdx.x * 256 + threadIdx.x) >> 5;   // node
    int l = threadIdx.x & 31;
    bool act = l < 10;
    float4 v = make_float4(-1e30f, -1e30f, -1e30f, -1e30f);
    if (act) v = add4(g_out2[w * 10 + l], ((const float4*)b2)[l]);
    float mx = act ? fmaxf(fmaxf(v.x, v.y), fmaxf(v.z, v.w)) : -1e30f;
    #pragma unroll
    for (int o = 16; o; o >>= 1) mx = fmaxf(mx, __shfl_xor_sync(0xffffffffu, mx, o));
    float s = 0.f;
    if (act) s = __expf(v.x - mx) + __expf(v.y - mx) + __expf(v.z - mx) + __expf(v.w - mx);
    #pragma unroll
    for (int o = 16; o; o >>= 1) s += __shfl_xor_sync(0xffffffffu, s, o);
    float lse = mx + logf(s);
    if (act)
        ((float4*)out)[w * 10 + l] =
            make_float4(v.x - lse, v.y - lse, v.z - lse, v.w - lse);
}

// ---------------- launch ----------------
extern "C" void kernel_launch(void* const* d_in, const int* in_sizes, int n_in,
                              void* d_out, int out_size)
{
    const float* x      = (const float*)d_in[0];
    const int*   eidx   = (const int*)d_in[1];
    const float* W1     = (const float*)d_in[2];
    const float* a_src1 = (const float*)d_in[3];
    const float* a_dst1 = (const float*)d_in[4];
    const float* b1     = (const float*)d_in[5];
    const float* W2     = (const float*)d_in[6];
    const float* a_src2 = (const float*)d_in[7];
    const float* a_dst2 = (const float*)d_in[8];
    const float* b2     = (const float*)d_in[9];
    const int* src = eidx;
    const int* dst = eidx + EE;
    float* out = (float*)d_out;

    zero_kernel<<<(NN * 32) / 256, 256>>>();                    // 12500 blocks
    gemm1_kernel<<<NN / 32, 256>>>(x, W1, a_src1, a_dst1);      // 3125
    edge1_l1<<<EE / 256, 256>>>(src, dst);                      // 6250
    edge2_l1<<<(EE * 32) / 256, 256>>>(src, dst);               // 200000
    fin1_kernel<<<(NN * 32) / 256, 256>>>(b1);                  // 12500
    gemm2_kernel<<<(NN + 255) / 256, 256>>>(W2, a_src2, a_dst2);// 391
    edge1_l2<<<EE / 256, 256>>>(src, dst);                      // 6250
    edge2_l2<<<(EE * 10) / 256, 256>>>(src, dst);               // 62500
    fin2_kernel<<<(NN * 32) / 256, 256>>>(b2, out);             // 12500
}

// round 2
// speedup vs baseline: 1.2399x; 1.2399x over previous
#include <cuda_runtime.h>
#include <cuda_bf16.h>
#include <math.h>

#define NN 100000
#define EE 1600000
#define EPSV 1e-16f
#define NEG_SLOPE 0.2f
#define FULL 0xffffffffu

// ---------------- scratch (device globals; allocation-free) ----------------
__device__ float4 g_h1[NN * 32];       // h1 [N,128]            51.2 MB
__device__ float  g_as1[NN * 8];       // alpha_src1 [N,8]       3.2 MB
__device__ float  g_ad1[NN * 8];       // alpha_dst1 [N,8]       3.2 MB
__device__ float4 g_out1[NN * 32];     // elu(out1) [N,128]     51.2 MB
__device__ float4 g_g2[NN * 10];       // g2 [N,40]               16 MB
__device__ float  g_as2[NN];           // alpha_src2 [N]
__device__ float  g_ad2[NN];           // alpha_dst2 [N]
// CSR sort scratch
__device__ int    g_deg[NN];
__device__ int    g_off[NN + 1];
__device__ int    g_pos[NN];
__device__ int    g_ssrc[EE];          // src sorted by dst      6.4 MB
__device__ int    g_bsum[128];
__device__ int    g_boff[128];

// ---------------- helpers ----------------
__device__ __forceinline__ void fma4(float4& a, float s, float4 b) {
    a.x += s * b.x; a.y += s * b.y; a.z += s * b.z; a.w += s * b.w;
}
__device__ __forceinline__ float dot4(float4 a, float4 b) {
    return a.x * b.x + a.y * b.y + a.z * b.z + a.w * b.w;
}
__device__ __forceinline__ float4 add4(float4 a, float4 b) {
    return make_float4(a.x + b.x, a.y + b.y, a.z + b.z, a.w + b.w);
}
__device__ __forceinline__ float leaky_exp(float e) {
    float t = e > 0.f ? e : NEG_SLOPE * e;
    return __expf(t);
}

// ---------------- 0. zero sort counters ----------------
__global__ __launch_bounds__(256) void zero_kernel() {
    int i = blockIdx.x * 256 + threadIdx.x;
    if (i < NN) { g_deg[i] = 0; g_pos[i] = 0; }
}

// ---------------- S1. histogram of dst ----------------
__global__ __launch_bounds__(256) void hist_kernel(const int* __restrict__ dst) {
    int i = blockIdx.x * 256 + threadIdx.x;
    atomicAdd(&g_deg[__ldcs(dst + i)], 1);
}

// ---------------- S2a. block-level exclusive scan of degrees ----------------
__global__ __launch_bounds__(1024) void scan1_kernel() {
    int t = threadIdx.x;
    int i = blockIdx.x * 1024 + t;
    int v = (i < NN) ? g_deg[i] : 0;
    int lane = t & 31, w = t >> 5;
    int x = v;
    #pragma unroll
    for (int o = 1; o < 32; o <<= 1) {
        int y = __shfl_up_sync(FULL, x, o);
        if (lane >= o) x += y;
    }
    __shared__ int wt[32];
    if (lane == 31) wt[w] = x;
    __syncthreads();
    if (w == 0) {
        int z = wt[lane];
        #pragma unroll
        for (int o = 1; o < 32; o <<= 1) {
            int y = __shfl_up_sync(FULL, z, o);
            if (lane >= o) z += y;
        }
        wt[lane] = z;
    }
    __syncthreads();
    int pre = (w ? wt[w - 1] : 0);
    if (i < NN) g_off[i] = pre + x - v;      // block-local exclusive
    if (t == 1023) g_bsum[blockIdx.x] = wt[31];
}

// ---------------- S2b. scan of 98 block sums ----------------
__global__ __launch_bounds__(128) void scan2_kernel() {
    __shared__ int s[98];
    int t = threadIdx.x;
    if (t < 98) s[t] = g_bsum[t];
    __syncthreads();
    if (t == 0) {
        int run = 0;
        for (int b = 0; b < 98; b++) { g_boff[b] = run; run += s[b]; }
        g_off[NN] = EE;
    }
}

// ---------------- S2c. add block offsets ----------------
__global__ __launch_bounds__(1024) void scan3_kernel() {
    int i = blockIdx.x * 1024 + threadIdx.x;
    if (i < NN) g_off[i] += g_boff[blockIdx.x];
}

// ---------------- S3. scatter src into CSR order ----------------
__global__ __launch_bounds__(256) void scatter_kernel(
    const int* __restrict__ src, const int* __restrict__ dst)
{
    int i = blockIdx.x * 256 + threadIdx.x;
    int d = __ldcs(dst + i);
    int s = __ldcs(src + i);
    int p = g_off[d] + atomicAdd(&g_pos[d], 1);
    g_ssrc[p] = s;
}

// ---------------- 1. GEMM1: h1 = x@W1 [128->128] + per-head alphas ----------
__global__ __launch_bounds__(256) void gemm1_kernel(
    const float* __restrict__ x, const float* __restrict__ W1,
    const float* __restrict__ a_src, const float* __restrict__ a_dst)
{
    __shared__ float4 sW[64 * 32];     // 32 KB
    __shared__ float  sx[32 * 65];
    const int tid = threadIdx.x;
    const int nl = tid >> 3, cg = tid & 7;
    const int nbase = blockIdx.x * 32;
    const float4* W4 = (const float4*)W1;

    float4 a0 = make_float4(0, 0, 0, 0), a1 = a0, a2 = a0, a3 = a0;

    for (int k0 = 0; k0 < 128; k0 += 64) {
        #pragma unroll
        for (int it = 0; it < 8; it++) {
            int f = tid + it * 256;
            sW[f] = W4[(k0 + (f >> 5)) * 32 + (f & 31)];
        }
        #pragma unroll
        for (int it = 0; it < 8; it++) {
            int f = tid + it * 256;
            int n = f >> 6, k = f & 63;
            sx[n * 65 + k] = x[(nbase + n) * 128 + k0 + k];
        }
        __syncthreads();
        #pragma unroll 8
        for (int r = 0; r < 64; r++) {
            float xv = sx[nl * 65 + r];
            const float4* wr = &sW[r * 32 + cg * 4];
            fma4(a0, xv, wr[0]); fma4(a1, xv, wr[1]);
            fma4(a2, xv, wr[2]); fma4(a3, xv, wr[3]);
        }
        __syncthreads();
    }

    const int node = nbase + nl;
    const float4* as4 = (const float4*)a_src;
    const float4* ad4 = (const float4*)a_dst;
    float ssrc = dot4(a0, as4[cg * 4 + 0]) + dot4(a1, as4[cg * 4 + 1])
               + dot4(a2, as4[cg * 4 + 2]) + dot4(a3, as4[cg * 4 + 3]);
    float sdst = dot4(a0, ad4[cg * 4 + 0]) + dot4(a1, ad4[cg * 4 + 1])
               + dot4(a2, ad4[cg * 4 + 2]) + dot4(a3, ad4[cg * 4 + 3]);
    g_h1[node * 32 + cg * 4 + 0] = a0;
    g_h1[node * 32 + cg * 4 + 1] = a1;
    g_h1[node * 32 + cg * 4 + 2] = a2;
    g_h1[node * 32 + cg * 4 + 3] = a3;
    g_as1[node * 8 + cg] = ssrc;
    g_ad1[node * 8 + cg] = sdst;
}

// ---------------- 2. L1 fused aggregate: warp per node ----------------------
// pass1: denominator per head (8 heads x 4 edges mapped over 32 lanes)
// pass2: acc[lane f4] += alpha(head=l>>2) * h1[src], then elu(acc+b1)
__global__ __launch_bounds__(256) void agg1_kernel(const float* __restrict__ b1)
{
    const int n = (blockIdx.x * 256 + threadIdx.x) >> 5;   // node (grid exact)
    const int l = threadIdx.x & 31;
    const int beg = g_off[n], end = g_off[n + 1];
    const int h = l & 7;
    const float ad1h = g_ad1[n * 8 + h];

    float den = 0.f;
    for (int base = beg; base < end; base += 32) {
        int je = min(32, end - base);
        int sj = (l < je) ? __ldg(&g_ssrc[base + l]) : 0;
        int nq = (je + 3) >> 2;
        for (int q = 0; q < nq; q++) {
            int ei = q * 4 + (l >> 3);
            int s = __shfl_sync(FULL, sj, min(ei, 31));
            if (ei < je) den += leaky_exp(g_as1[s * 8 + h] + ad1h);
        }
    }
    den += __shfl_xor_sync(FULL, den, 8);
    den += __shfl_xor_sync(FULL, den, 16);
    const float rinv = 1.f / (__shfl_sync(FULL, den, l >> 2) + EPSV);
    const float adp = g_ad1[n * 8 + (l >> 2)];

    float4 acc = make_float4(0.f, 0.f, 0.f, 0.f);
    for (int base = beg; base < end; base += 32) {
        int je = min(32, end - base);
        int sj = (l < je) ? __ldg(&g_ssrc[base + l]) : 0;
        for (int k = 0; k < je; k++) {
            int s = __shfl_sync(FULL, sj, k);
            float alpha = leaky_exp(g_as1[s * 8 + (l >> 2)] + adp) * rinv;
            fma4(acc, alpha, g_h1[s * 32 + l]);
        }
    }
    float4 v = add4(acc, ((const float4*)b1)[l]);
    v.x = v.x > 0.f ? v.x : __expf(v.x) - 1.f;
    v.y = v.y > 0.f ? v.y : __expf(v.y) - 1.f;
    v.z = v.z > 0.f ? v.z : __expf(v.z) - 1.f;
    v.w = v.w > 0.f ? v.w : __expf(v.w) - 1.f;
    g_out1[n * 32 + l] = v;
}

// ---------------- 3. GEMM2: g2 = elu_h @ W2 [128->40] + scalar alphas -------
__global__ __launch_bounds__(256) void gemm2_kernel(
    const float* __restrict__ W2, const float* __restrict__ a_src,
    const float* __restrict__ a_dst)
{
    __shared__ float4 sW[128 * 10];
    __shared__ float4 sas[10], sad[10];
    __shared__ float  sx[256 * 17];
    const int tid = threadIdx.x;
    const int node = blockIdx.x * 256 + tid;
    const float4* W4 = (const float4*)W2;
    #pragma unroll
    for (int it = 0; it < 5; it++) sW[tid + it * 256] = W4[tid + it * 256];
    if (tid < 10) { sas[tid] = ((const float4*)a_src)[tid];
                    sad[tid] = ((const float4*)a_dst)[tid]; }
    const float* hin = (const float*)g_out1;

    float4 acc[10];
    #pragma unroll
    for (int j = 0; j < 10; j++) acc[j] = make_float4(0, 0, 0, 0);

    for (int kc = 0; kc < 8; kc++) {
        __syncthreads();
        #pragma unroll
        for (int it = 0; it < 16; it++) {
            int f = tid + it * 256;
            int nl2 = f >> 4, k = f & 15;
            int gn = blockIdx.x * 256 + nl2;
            sx[nl2 * 17 + k] = (gn < NN) ? hin[(size_t)gn * 128 + kc * 16 + k] : 0.f;
        }
        __syncthreads();
        #pragma unroll
        for (int k = 0; k < 16; k++) {
            float xv = sx[tid * 17 + k];
            const float4* wr = &sW[(kc * 16 + k) * 10];
            #pragma unroll
            for (int j = 0; j < 10; j++) fma4(acc[j], xv, wr[j]);
        }
    }
    if (node < NN) {
        float s = 0.f, d = 0.f;
        #pragma unroll
        for (int j = 0; j < 10; j++) { s += dot4(acc[j], sas[j]); d += dot4(acc[j], sad[j]); }
        #pragma unroll
        for (int j = 0; j < 10; j++) g_g2[node * 10 + j] = acc[j];
        g_as2[node] = s;
        g_ad2[node] = d;
    }
}

// ---------------- 4. L2 fused aggregate + bias + log_softmax ---------------
__global__ __launch_bounds__(256) void agg2_kernel(
    const float* __restrict__ b2, float* __restrict__ out)
{
    const int n = (blockIdx.x * 256 + threadIdx.x) >> 5;
    const int l = threadIdx.x & 31;
    const int beg = g_off[n], end = g_off[n + 1];
    const float ad2n = g_ad2[n];

    float den = 0.f;
    for (int base = beg; base < end; base += 32) {
        int je = min(32, end - base);
        if (l < je) {
            int s = __ldg(&g_ssrc[base + l]);
            den += leaky_exp(g_as2[s] + ad2n);
        }
    }
    #pragma unroll
    for (int o = 16; o; o >>= 1) den += __shfl_xor_sync(FULL, den, o);
    const float rinv = 1.f / (den + EPSV);

    float4 acc = make_float4(0.f, 0.f, 0.f, 0.f);
    const bool act = l < 10;
    for (int base = beg; base < end; base += 32) {
        int je = min(32, end - base);
        int sj = (l < je) ? __ldg(&g_ssrc[base + l]) : 0;
        for (int k = 0; k < je; k++) {
            int s = __shfl_sync(FULL, sj, k);
            float alpha = leaky_exp(g_as2[s] + ad2n) * rinv;
            if (act) fma4(acc, alpha, g_g2[s * 10 + l]);
        }
    }

    float4 v = make_float4(-1e30f, -1e30f, -1e30f, -1e30f);
    if (act) v = add4(acc, ((const float4*)b2)[l]);
    float mx = act ? fmaxf(fmaxf(v.x, v.y), fmaxf(v.z, v.w)) : -1e30f;
    #pragma unroll
    for (int o = 16; o; o >>= 1) mx = fmaxf(mx, __shfl_xor_sync(FULL, mx, o));
    float sm = 0.f;
    if (act) sm = __expf(v.x - mx) + __expf(v.y - mx) + __expf(v.z - mx) + __expf(v.w - mx);
    #pragma unroll
    for (int o = 16; o; o >>= 1) sm += __shfl_xor_sync(FULL, sm, o);
    float lse = mx + logf(sm);
    if (act)
        ((float4*)out)[n * 10 + l] =
            make_float4(v.x - lse, v.y - lse, v.z - lse, v.w - lse);
}

// ---------------- launch ----------------
extern "C" void kernel_launch(void* const* d_in, const int* in_sizes, int n_in,
                              void* d_out, int out_size)
{
    const float* x      = (const float*)d_in[0];
    const int*   eidx   = (const int*)d_in[1];
    const float* W1     = (const float*)d_in[2];
    const float* a_src1 = (const float*)d_in[3];
    const float* a_dst1 = (const float*)d_in[4];
    const float* b1     = (const float*)d_in[5];
    const float* W2     = (const float*)d_in[6];
    const float* a_src2 = (const float*)d_in[7];
    const float* a_dst2 = (const float*)d_in[8];
    const float* b2     = (const float*)d_in[9];
    const int* src = eidx;
    const int* dst = eidx + EE;
    float* out = (float*)d_out;

    zero_kernel<<<(NN + 255) / 256, 256>>>();
    hist_kernel<<<EE / 256, 256>>>(dst);
    scan1_kernel<<<98, 1024>>>();
    scan2_kernel<<<1, 128>>>();
    scan3_kernel<<<98, 1024>>>();
    scatter_kernel<<<EE / 256, 256>>>(src, dst);

    gemm1_kernel<<<NN / 32, 256>>>(x, W1, a_src1, a_dst1);
    agg1_kernel<<<NN / 8, 256>>>(b1);
    gemm2_kernel<<<(NN + 255) / 256, 256>>>(W2, a_src2, a_dst2);
    agg2_kernel<<<NN / 8, 256>>>(b2, out);
}

// round 3
// speedup vs baseline: 1.2471x; 1.0058x over previous
#include <cuda_runtime.h>
#include <cuda_bf16.h>
#include <math.h>

#define NN 100000
#define EE 1600000
#define EPSV 1e-16f
#define NEG_SLOPE 0.2f
#define FULL 0xffffffffu

// ---------------- scratch (device globals; allocation-free) ----------------
__device__ float4 g_h1[NN * 32];       // h1 [N,128]            51.2 MB
__device__ float  g_as1[NN * 8];       // alpha_src1 [N,8]       3.2 MB
__device__ float  g_ad1[NN * 8];       // alpha_dst1 [N,8]       3.2 MB
__device__ float4 g_out1[NN * 32];     // elu(out1) [N,128]     51.2 MB
__device__ float4 g_g2[NN * 10];       // g2 [N,40]               16 MB
__device__ float  g_as2[NN];           // alpha_src2 [N]
__device__ float  g_ad2[NN];           // alpha_dst2 [N]
// CSR sort scratch
__device__ int    g_deg[NN];
__device__ int    g_off[NN + 1];
__device__ int    g_pos[NN];
__device__ int    g_ssrc[EE];          // src sorted by dst      6.4 MB
__device__ int    g_bsum[128];

// ---------------- helpers ----------------
__device__ __forceinline__ void fma4(float4& a, float s, float4 b) {
    a.x += s * b.x; a.y += s * b.y; a.z += s * b.z; a.w += s * b.w;
}
__device__ __forceinline__ float dot4(float4 a, float4 b) {
    return a.x * b.x + a.y * b.y + a.z * b.z + a.w * b.w;
}
__device__ __forceinline__ float4 add4(float4 a, float4 b) {
    return make_float4(a.x + b.x, a.y + b.y, a.z + b.z, a.w + b.w);
}
__device__ __forceinline__ float leaky_exp(float e) {
    float t = e > 0.f ? e : NEG_SLOPE * e;
    return __expf(t);
}

// ---------------- 0. zero sort counters ----------------
__global__ __launch_bounds__(256) void zero_kernel() {
    int i = blockIdx.x * 256 + threadIdx.x;
    if (i < NN) { g_deg[i] = 0; g_pos[i] = 0; }
}

// ---------------- S1. histogram of dst ----------------
__global__ __launch_bounds__(256) void hist_kernel(const int* __restrict__ dst) {
    int i = blockIdx.x * 256 + threadIdx.x;
    atomicAdd(&g_deg[__ldcs(dst + i)], 1);
}

// ---------------- S2a. block-level exclusive scan of degrees ----------------
__global__ __launch_bounds__(1024) void scan1_kernel() {
    int t = threadIdx.x;
    int i = blockIdx.x * 1024 + t;
    int v = (i < NN) ? g_deg[i] : 0;
    int lane = t & 31, w = t >> 5;
    int x = v;
    #pragma unroll
    for (int o = 1; o < 32; o <<= 1) {
        int y = __shfl_up_sync(FULL, x, o);
        if (lane >= o) x += y;
    }
    __shared__ int wt[32];
    if (lane == 31) wt[w] = x;
    __syncthreads();
    if (w == 0) {
        int z = wt[lane];
        #pragma unroll
        for (int o = 1; o < 32; o <<= 1) {
            int y = __shfl_up_sync(FULL, z, o);
            if (lane >= o) z += y;
        }
        wt[lane] = z;
    }
    __syncthreads();
    int pre = (w ? wt[w - 1] : 0);
    if (i < NN) g_off[i] = pre + x - v;      // block-local exclusive
    if (t == 1023) g_bsum[blockIdx.x] = wt[31];
}

// ---------------- S2b. add block prefix (scan2+scan3 fused) ----------------
__global__ __launch_bounds__(1024) void scanB_kernel() {
    __shared__ int s[128];
    __shared__ int blockpre;
    int t = threadIdx.x;
    if (t < 128) s[t] = (t < 98) ? g_bsum[t] : 0;
    __syncthreads();
    if (t == 0) {
        int run = 0;
        for (int b = 0; b < blockIdx.x; b++) run += s[b];
        blockpre = run;
    }
    __syncthreads();
    int i = blockIdx.x * 1024 + t;
    if (i < NN) g_off[i] += blockpre;
    if (i == 0) g_off[NN] = EE;
}

// ---------------- S3. scatter src into CSR order ----------------
__global__ __launch_bounds__(256) void scatter_kernel(
    const int* __restrict__ src, const int* __restrict__ dst)
{
    int i = blockIdx.x * 256 + threadIdx.x;
    int d = __ldcs(dst + i);
    int s = __ldcs(src + i);
    int p = g_off[d] + atomicAdd(&g_pos[d], 1);
    __stcs(&g_ssrc[p], s);
}

// ---------------- 1. GEMM1: h1 = x@W1 [128->128] + per-head alphas ----------
__global__ __launch_bounds__(256) void gemm1_kernel(
    const float* __restrict__ x, const float* __restrict__ W1,
    const float* __restrict__ a_src, const float* __restrict__ a_dst)
{
    __shared__ float4 sW[64 * 32];     // 32 KB
    __shared__ float  sx[32 * 65];
    const int tid = threadIdx.x;
    const int nl = tid >> 3, cg = tid & 7;
    const int nbase = blockIdx.x * 32;
    const float4* W4 = (const float4*)W1;

    float4 a0 = make_float4(0, 0, 0, 0), a1 = a0, a2 = a0, a3 = a0;

    for (int k0 = 0; k0 < 128; k0 += 64) {
        #pragma unroll
        for (int it = 0; it < 8; it++) {
            int f = tid + it * 256;
            sW[f] = W4[(k0 + (f >> 5)) * 32 + (f & 31)];
        }
        #pragma unroll
        for (int it = 0; it < 8; it++) {
            int f = tid + it * 256;
            int n = f >> 6, k = f & 63;
            sx[n * 65 + k] = x[(nbase + n) * 128 + k0 + k];
        }
        __syncthreads();
        #pragma unroll 8
        for (int r = 0; r < 64; r++) {
            float xv = sx[nl * 65 + r];
            const float4* wr = &sW[r * 32 + cg * 4];
            fma4(a0, xv, wr[0]); fma4(a1, xv, wr[1]);
            fma4(a2, xv, wr[2]); fma4(a3, xv, wr[3]);
        }
        __syncthreads();
    }

    const int node = nbase + nl;
    const float4* as4 = (const float4*)a_src;
    const float4* ad4 = (const float4*)a_dst;
    float ssrc = dot4(a0, as4[cg * 4 + 0]) + dot4(a1, as4[cg * 4 + 1])
               + dot4(a2, as4[cg * 4 + 2]) + dot4(a3, as4[cg * 4 + 3]);
    float sdst = dot4(a0, ad4[cg * 4 + 0]) + dot4(a1, ad4[cg * 4 + 1])
               + dot4(a2, ad4[cg * 4 + 2]) + dot4(a3, ad4[cg * 4 + 3]);
    g_h1[node * 32 + cg * 4 + 0] = a0;
    g_h1[node * 32 + cg * 4 + 1] = a1;
    g_h1[node * 32 + cg * 4 + 2] = a2;
    g_h1[node * 32 + cg * 4 + 3] = a3;
    g_as1[node * 8 + cg] = ssrc;
    g_ad1[node * 8 + cg] = sdst;
}

// ---------------- 2. L1 fused aggregate: warp per node, ONE pass ------------
// acc[lane] += ex * h1[src]; den += ex  (all lanes of a head group compute the
// same den); at the end acc *= 1/(den+eps), then elu(acc + b1).
__global__ __launch_bounds__(256) void agg1_kernel(const float* __restrict__ b1)
{
    const int n = (blockIdx.x * 256 + threadIdx.x) >> 5;   // node (grid exact)
    const int l = threadIdx.x & 31;
    const int beg = g_off[n], end = g_off[n + 1];
    const int head = l >> 2;
    const float adp = g_ad1[n * 8 + head];

    float den = 0.f;
    float4 acc = make_float4(0.f, 0.f, 0.f, 0.f);

    for (int base = beg; base < end; base += 32) {
        const int je = min(32, end - base);
        const int sj = (l < je) ? __ldg(&g_ssrc[base + l]) : 0;
        int k = 0;
        #pragma unroll 1
        for (; k + 4 <= je; k += 4) {
            int s0 = __shfl_sync(FULL, sj, k);
            int s1 = __shfl_sync(FULL, sj, k + 1);
            int s2 = __shfl_sync(FULL, sj, k + 2);
            int s3 = __shfl_sync(FULL, sj, k + 3);
            float e0 = leaky_exp(__ldg(&g_as1[s0 * 8 + head]) + adp);
            float e1 = leaky_exp(__ldg(&g_as1[s1 * 8 + head]) + adp);
            float e2 = leaky_exp(__ldg(&g_as1[s2 * 8 + head]) + adp);
            float e3 = leaky_exp(__ldg(&g_as1[s3 * 8 + head]) + adp);
            float4 h0 = g_h1[s0 * 32 + l];
            float4 h1v = g_h1[s1 * 32 + l];
            float4 h2 = g_h1[s2 * 32 + l];
            float4 h3 = g_h1[s3 * 32 + l];
            den += (e0 + e1) + (e2 + e3);
            fma4(acc, e0, h0); fma4(acc, e1, h1v);
            fma4(acc, e2, h2); fma4(acc, e3, h3);
        }
        for (; k < je; k++) {
            int s = __shfl_sync(FULL, sj, k);
            float e = leaky_exp(__ldg(&g_as1[s * 8 + head]) + adp);
            den += e;
            fma4(acc, e, g_h1[s * 32 + l]);
        }
    }
    const float rinv = 1.f / (den + EPSV);
    float4 v = ((const float4*)b1)[l];
    v.x += acc.x * rinv; v.y += acc.y * rinv;
    v.z += acc.z * rinv; v.w += acc.w * rinv;
    v.x = v.x > 0.f ? v.x : __expf(v.x) - 1.f;
    v.y = v.y > 0.f ? v.y : __expf(v.y) - 1.f;
    v.z = v.z > 0.f ? v.z : __expf(v.z) - 1.f;
    v.w = v.w > 0.f ? v.w : __expf(v.w) - 1.f;
    g_out1[n * 32 + l] = v;
}

// ---------------- 3. GEMM2: g2 = elu_h @ W2 [128->40] + scalar alphas -------
__global__ __launch_bounds__(256) void gemm2_kernel(
    const float* __restrict__ W2, const float* __restrict__ a_src,
    const float* __restrict__ a_dst)
{
    __shared__ float4 sW[128 * 10];
    __shared__ float4 sas[10], sad[10];
    __shared__ float  sx[256 * 17];
    const int tid = threadIdx.x;
    const int node = blockIdx.x * 256 + tid;
    const float4* W4 = (const float4*)W2;
    #pragma unroll
    for (int it = 0; it < 5; it++) sW[tid + it * 256] = W4[tid + it * 256];
    if (tid < 10) { sas[tid] = ((const float4*)a_src)[tid];
                    sad[tid] = ((const float4*)a_dst)[tid]; }
    const float* hin = (const float*)g_out1;

    float4 acc[10];
    #pragma unroll
    for (int j = 0; j < 10; j++) acc[j] = make_float4(0, 0, 0, 0);

    for (int kc = 0; kc < 8; kc++) {
        __syncthreads();
        #pragma unroll
        for (int it = 0; it < 16; it++) {
            int f = tid + it * 256;
            int nl2 = f >> 4, k = f & 15;
            int gn = blockIdx.x * 256 + nl2;
            sx[nl2 * 17 + k] = (gn < NN) ? hin[(size_t)gn * 128 + kc * 16 + k] : 0.f;
        }
        __syncthreads();
        #pragma unroll
        for (int k = 0; k < 16; k++) {
            float xv = sx[tid * 17 + k];
            const float4* wr = &sW[(kc * 16 + k) * 10];
            #pragma unroll
            for (int j = 0; j < 10; j++) fma4(acc[j], xv, wr[j]);
        }
    }
    if (node < NN) {
        float s = 0.f, d = 0.f;
        #pragma unroll
        for (int j = 0; j < 10; j++) { s += dot4(acc[j], sas[j]); d += dot4(acc[j], sad[j]); }
        #pragma unroll
        for (int j = 0; j < 10; j++) g_g2[node * 10 + j] = acc[j];
        g_as2[node] = s;
        g_ad2[node] = d;
    }
}

// ---------------- 4. L2 fused aggregate (one pass) + bias + log_softmax -----
__global__ __launch_bounds__(256) void agg2_kernel(
    const float* __restrict__ b2, float* __restrict__ out)
{
    const int n = (blockIdx.x * 256 + threadIdx.x) >> 5;
    const int l = threadIdx.x & 31;
    const int beg = g_off[n], end = g_off[n + 1];
    const float ad2n = g_ad2[n];
    const bool act = l < 10;

    float den = 0.f;
    float4 acc = make_float4(0.f, 0.f, 0.f, 0.f);

    for (int base = beg; base < end; base += 32) {
        const int je = min(32, end - base);
        const int sj = (l < je) ? __ldg(&g_ssrc[base + l]) : 0;
        int k = 0;
        #pragma unroll 1
        for (; k + 4 <= je; k += 4) {
            int s0 = __shfl_sync(FULL, sj, k);
            int s1 = __shfl_sync(FULL, sj, k + 1);
            int s2 = __shfl_sync(FULL, sj, k + 2);
            int s3 = __shfl_sync(FULL, sj, k + 3);
            float e0 = leaky_exp(__ldg(&g_as2[s0]) + ad2n);
            float e1 = leaky_exp(__ldg(&g_as2[s1]) + ad2n);
            float e2 = leaky_exp(__ldg(&g_as2[s2]) + ad2n);
            float e3 = leaky_exp(__ldg(&g_as2[s3]) + ad2n);
            den += (e0 + e1) + (e2 + e3);
            if (act) {
                fma4(acc, e0, g_g2[s0 * 10 + l]);
                fma4(acc, e1, g_g2[s1 * 10 + l]);
                fma4(acc, e2, g_g2[s2 * 10 + l]);
                fma4(acc, e3, g_g2[s3 * 10 + l]);
            }
        }
        for (; k < je; k++) {
            int s = __shfl_sync(FULL, sj, k);
            float e = leaky_exp(__ldg(&g_as2[s]) + ad2n);
            den += e;
            if (act) fma4(acc, e, g_g2[s * 10 + l]);
        }
    }
    const float rinv = 1.f / (den + EPSV);

    float4 v = make_float4(-1e30f, -1e30f, -1e30f, -1e30f);
    if (act) {
        v = ((const float4*)b2)[l];
        v.x += acc.x * rinv; v.y += acc.y * rinv;
        v.z += acc.z * rinv; v.w += acc.w * rinv;
    }
    float mx = act ? fmaxf(fmaxf(v.x, v.y), fmaxf(v.z, v.w)) : -1e30f;
    #pragma unroll
    for (int o = 16; o; o >>= 1) mx = fmaxf(mx, __shfl_xor_sync(FULL, mx, o));
    float sm = 0.f;
    if (act) sm = __expf(v.x - mx) + __expf(v.y - mx) + __expf(v.z - mx) + __expf(v.w - mx);
    #pragma unroll
    for (int o = 16; o; o >>= 1) sm += __shfl_xor_sync(FULL, sm, o);
    float lse = mx + logf(sm);
    if (act)
        ((float4*)out)[n * 10 + l] =
            make_float4(v.x - lse, v.y - lse, v.z - lse, v.w - lse);
}

// ---------------- launch ----------------
extern "C" void kernel_launch(void* const* d_in, const int* in_sizes, int n_in,
                              void* d_out, int out_size)
{
    const float* x      = (const float*)d_in[0];
    const int*   eidx   = (const int*)d_in[1];
    const float* W1     = (const float*)d_in[2];
    const float* a_src1 = (const float*)d_in[3];
    const float* a_dst1 = (const float*)d_in[4];
    const float* b1     = (const float*)d_in[5];
    const float* W2     = (const float*)d_in[6];
    const float* a_src2 = (const float*)d_in[7];
    const float* a_dst2 = (const float*)d_in[8];
    const float* b2     = (const float*)d_in[9];
    const int* src = eidx;
    const int* dst = eidx + EE;
    float* out = (float*)d_out;

    zero_kernel<<<(NN + 255) / 256, 256>>>();                   // 1
    hist_kernel<<<EE / 256, 256>>>(dst);                        // 2
    scan1_kernel<<<98, 1024>>>();                               // 3
    gemm1_kernel<<<NN / 32, 256>>>(x, W1, a_src1, a_dst1);      // 4 (ncu slot)
    scanB_kernel<<<98, 1024>>>();                               // 5
    scatter_kernel<<<EE / 256, 256>>>(src, dst);                // 6
    agg1_kernel<<<NN / 8, 256>>>(b1);                           // 7
    gemm2_kernel<<<(NN + 255) / 256, 256>>>(W2, a_src2, a_dst2);// 8
    agg2_kernel<<<NN / 8, 256>>>(b2, out);                      // 9
}

// round 5
// speedup vs baseline: 3.6990x; 2.9660x over previous
#include <cuda_runtime.h>
#include <cuda_bf16.h>
#include <math.h>

#define NN 100000
#define EE 1600000
#define EPSV 1e-16f
#define NEG_SLOPE 0.2f
#define FULL 0xffffffffu

// ---------------- scratch (device globals; allocation-free) ----------------
__device__ float4 g_h1[NN * 32];       // h1 [N,128]            51.2 MB
__device__ float  g_as1[NN * 8];       // alpha_src1 [N,8]       3.2 MB
__device__ float  g_ad1[NN * 8];       // alpha_dst1 [N,8]       3.2 MB
__device__ float4 g_out1[NN * 32];     // elu(out1) [N,128]     51.2 MB
__device__ float4 g_g2[NN * 10];       // g2 [N,40]               16 MB
__device__ float  g_as2[NN];           // alpha_src2 [N]
__device__ float  g_ad2[NN];           // alpha_dst2 [N]
// CSR sort scratch
__device__ int    g_deg[NN];
__device__ int    g_off[NN + 1];
__device__ int    g_pos[NN];
__device__ int    g_ssrc[EE];          // src sorted by dst      6.4 MB
__device__ int    g_bsum[128];

// ---------------- helpers ----------------
__device__ __forceinline__ void fma4(float4& a, float s, float4 b) {
    a.x += s * b.x; a.y += s * b.y; a.z += s * b.z; a.w += s * b.w;
}
__device__ __forceinline__ float dot4(float4 a, float4 b) {
    return a.x * b.x + a.y * b.y + a.z * b.z + a.w * b.w;
}
__device__ __forceinline__ float leaky_exp(float e) {
    float t = e > 0.f ? e : NEG_SLOPE * e;
    return __expf(t);
}

// ---------------- 0. zero sort counters ----------------
__global__ __launch_bounds__(256) void zero_kernel() {
    int i = blockIdx.x * 256 + threadIdx.x;
    if (i < NN) { g_deg[i] = 0; g_pos[i] = 0; }
}

// ---------------- S1. histogram of dst ----------------
__global__ __launch_bounds__(256) void hist_kernel(const int* __restrict__ dst) {
    int i = blockIdx.x * 256 + threadIdx.x;
    atomicAdd(&g_deg[__ldcs(dst + i)], 1);
}

// ---------------- S2a. block-level exclusive scan of degrees ----------------
__global__ __launch_bounds__(1024) void scan1_kernel() {
    int t = threadIdx.x;
    int i = blockIdx.x * 1024 + t;
    int v = (i < NN) ? g_deg[i] : 0;
    int lane = t & 31, w = t >> 5;
    int x = v;
    #pragma unroll
    for (int o = 1; o < 32; o <<= 1) {
        int y = __shfl_up_sync(FULL, x, o);
        if (lane >= o) x += y;
    }
    __shared__ int wt[32];
    if (lane == 31) wt[w] = x;
    __syncthreads();
    if (w == 0) {
        int z = wt[lane];
        #pragma unroll
        for (int o = 1; o < 32; o <<= 1) {
            int y = __shfl_up_sync(FULL, z, o);
            if (lane >= o) z += y;
        }
        wt[lane] = z;
    }
    __syncthreads();
    int pre = (w ? wt[w - 1] : 0);
    if (i < NN) g_off[i] = pre + x - v;      // block-local exclusive
    if (t == 1023) g_bsum[blockIdx.x] = wt[31];
}

// ---------------- S2b. add block prefix (scan2+scan3 fused) ----------------
__global__ __launch_bounds__(1024) void scanB_kernel() {
    __shared__ int s[128];
    __shared__ int blockpre;
    int t = threadIdx.x;
    if (t < 128) s[t] = (t < 98) ? g_bsum[t] : 0;
    __syncthreads();
    if (t == 0) {
        int run = 0;
        for (int b = 0; b < blockIdx.x; b++) run += s[b];
        blockpre = run;
    }
    __syncthreads();
    int i = blockIdx.x * 1024 + t;
    if (i < NN) g_off[i] += blockpre;
    if (i == 0) g_off[NN] = EE;
}

// ---------------- S3. scatter src into CSR order ----------------
__global__ __launch_bounds__(256) void scatter_kernel(
    const int* __restrict__ src, const int* __restrict__ dst)
{
    int i = blockIdx.x * 256 + threadIdx.x;
    int d = __ldcs(dst + i);
    int s = __ldcs(src + i);
    int p = g_off[d] + atomicAdd(&g_pos[d], 1);
    __stcs(&g_ssrc[p], s);
}

// ---------------- 1. GEMM1 (register-tiled): h1 = x@W1 + per-head alphas ----
// Block: 64 nodes x 128 cols, K=128 in one stage. 256 threads.
// Thread (cx = tid&31, ny = tid>>5): 8 nodes (ny*8..+7) x 4 cols (cx*4..+3).
// Dynamic smem: sW[128k x 128c] (64 KB) + sx[64n x 128k] (32 KB) = 96 KB.
__global__ __launch_bounds__(256) void gemm1_kernel(
    const float* __restrict__ x, const float* __restrict__ W1,
    const float* __restrict__ a_src, const float* __restrict__ a_dst)
{
    extern __shared__ float smem[];
    float4* sW4 = (float4*)smem;                 // [k*32 + c4]
    float4* sx4 = (float4*)(smem + 128 * 128);   // [n*32 + k4]
    const int tid = threadIdx.x;
    const int cx = tid & 31;      // col quad
    const int ny = tid >> 5;      // node group of 8
    const int nbase = blockIdx.x * 64;
    const float4* W4 = (const float4*)W1;
    const float4* x4 = (const float4*)x;

    #pragma unroll
    for (int it = 0; it < 16; it++)              // W: 4096 f4
        sW4[tid + it * 256] = W4[tid + it * 256];
    #pragma unroll
    for (int it = 0; it < 8; it++) {             // x: 2048 f4
        int f = tid + it * 256;
        int gn = nbase + (f >> 5);
        sx4[f] = (gn < NN) ? x4[(size_t)gn * 32 + (f & 31)]
                           : make_float4(0.f, 0.f, 0.f, 0.f);
    }
    __syncthreads();

    float4 c[8];
    #pragma unroll
    for (int i = 0; i < 8; i++) c[i] = make_float4(0.f, 0.f, 0.f, 0.f);

    #pragma unroll 4
    for (int k = 0; k < 128; k += 4) {
        float4 w0 = sW4[(k + 0) * 32 + cx];
        float4 w1 = sW4[(k + 1) * 32 + cx];
        float4 w2 = sW4[(k + 2) * 32 + cx];
        float4 w3 = sW4[(k + 3) * 32 + cx];
        #pragma unroll
        for (int i = 0; i < 8; i++) {
            float4 xv = sx4[(ny * 8 + i) * 32 + (k >> 2)];   // warp broadcast
            fma4(c[i], xv.x, w0); fma4(c[i], xv.y, w1);
            fma4(c[i], xv.z, w2); fma4(c[i], xv.w, w3);
        }
    }

    // epilogue: store h1 + per-head alpha dots (head = cx>>2, quarter cq = cx&3)
    const int head = cx >> 2, cq = cx & 3;
    const float4 asv = ((const float4*)a_src)[head * 4 + cq];
    const float4 adv = ((const float4*)a_dst)[head * 4 + cq];
    #pragma unroll
    for (int i = 0; i < 8; i++) {
        int gn = nbase + ny * 8 + i;
        float ps = dot4(c[i], asv);
        float pd = dot4(c[i], adv);
        ps += __shfl_xor_sync(FULL, ps, 1); ps += __shfl_xor_sync(FULL, ps, 2);
        pd += __shfl_xor_sync(FULL, pd, 1); pd += __shfl_xor_sync(FULL, pd, 2);
        if (gn < NN) {
            g_h1[gn * 32 + cx] = c[i];
            if (cq == 0) { g_as1[gn * 8 + head] = ps; g_ad1[gn * 8 + head] = pd; }
        }
    }
}

// ---------------- 2. L1 fused aggregate: warp per node, ONE pass ------------
__global__ __launch_bounds__(256) void agg1_kernel(const float* __restrict__ b1)
{
    const int n = (blockIdx.x * 256 + threadIdx.x) >> 5;   // node (grid exact)
    const int l = threadIdx.x & 31;
    const int beg = g_off[n], end = g_off[n + 1];
    const int head = l >> 2;
    const float adp = g_ad1[n * 8 + head];

    float den = 0.f;
    float4 acc = make_float4(0.f, 0.f, 0.f, 0.f);

    for (int base = beg; base < end; base += 32) {
        const int je = min(32, end - base);
        const int sj = (l < je) ? __ldg(&g_ssrc[base + l]) : 0;
        int k = 0;
        #pragma unroll 1
        for (; k + 4 <= je; k += 4) {
            int s0 = __shfl_sync(FULL, sj, k);
            int s1 = __shfl_sync(FULL, sj, k + 1);
            int s2 = __shfl_sync(FULL, sj, k + 2);
            int s3 = __shfl_sync(FULL, sj, k + 3);
            float e0 = leaky_exp(__ldg(&g_as1[s0 * 8 + head]) + adp);
            float e1 = leaky_exp(__ldg(&g_as1[s1 * 8 + head]) + adp);
            float e2 = leaky_exp(__ldg(&g_as1[s2 * 8 + head]) + adp);
            float e3 = leaky_exp(__ldg(&g_as1[s3 * 8 + head]) + adp);
            float4 h0 = g_h1[s0 * 32 + l];
            float4 h1v = g_h1[s1 * 32 + l];
            float4 h2 = g_h1[s2 * 32 + l];
            float4 h3 = g_h1[s3 * 32 + l];
            den += (e0 + e1) + (e2 + e3);
            fma4(acc, e0, h0); fma4(acc, e1, h1v);
            fma4(acc, e2, h2); fma4(acc, e3, h3);
        }
        for (; k < je; k++) {
            int s = __shfl_sync(FULL, sj, k);
            float e = leaky_exp(__ldg(&g_as1[s * 8 + head]) + adp);
            den += e;
            fma4(acc, e, g_h1[s * 32 + l]);
        }
    }
    const float rinv = 1.f / (den + EPSV);
    float4 v = ((const float4*)b1)[l];
    v.x += acc.x * rinv; v.y += acc.y * rinv;
    v.z += acc.z * rinv; v.w += acc.w * rinv;
    v.x = v.x > 0.f ? v.x : __expf(v.x) - 1.f;
    v.y = v.y > 0.f ? v.y : __expf(v.y) - 1.f;
    v.z = v.z > 0.f ? v.z : __expf(v.z) - 1.f;
    v.w = v.w > 0.f ? v.w : __expf(v.w) - 1.f;
    g_out1[n * 32 + l] = v;
}

// ---------------- 3. GEMM2: g2 = elu_h @ W2 [128->40] + scalar alphas -------
__global__ __launch_bounds__(256) void gemm2_kernel(
    const float* __restrict__ W2, const float* __restrict__ a_src,
    const float* __restrict__ a_dst)
{
    __shared__ float4 sW[128 * 10];
    __shared__ float4 sas[10], sad[10];
    __shared__ float  sx[256 * 17];
    const int tid = threadIdx.x;
    const int node = blockIdx.x * 256 + tid;
    const float4* W4 = (const float4*)W2;
    #pragma unroll
    for (int it = 0; it < 5; it++) sW[tid + it * 256] = W4[tid + it * 256];
    if (tid < 10) { sas[tid] = ((const float4*)a_src)[tid];
                    sad[tid] = ((const float4*)a_dst)[tid]; }
    const float* hin = (const float*)g_out1;

    float4 acc[10];
    #pragma unroll
    for (int j = 0; j < 10; j++) acc[j] = make_float4(0, 0, 0, 0);

    for (int kc = 0; kc < 8; kc++) {
        __syncthreads();
        #pragma unroll
        for (int it = 0; it < 16; it++) {
            int f = tid + it * 256;
            int nl2 = f >> 4, k = f & 15;
            int gn = blockIdx.x * 256 + nl2;
            sx[nl2 * 17 + k] = (gn < NN) ? hin[(size_t)gn * 128 + kc * 16 + k] : 0.f;
        }
        __syncthreads();
        #pragma unroll
        for (int k = 0; k < 16; k++) {
            float xv = sx[tid * 17 + k];
            const float4* wr = &sW[(kc * 16 + k) * 10];
            #pragma unroll
            for (int j = 0; j < 10; j++) fma4(acc[j], xv, wr[j]);
        }
    }
    if (node < NN) {
        float s = 0.f, d = 0.f;
        #pragma unroll
        for (int j = 0; j < 10; j++) { s += dot4(acc[j], sas[j]); d += dot4(acc[j], sad[j]); }
        #pragma unroll
        for (int j = 0; j < 10; j++) g_g2[node * 10 + j] = acc[j];
        g_as2[node] = s;
        g_ad2[node] = d;
    }
}

// ---------------- 4. L2 fused aggregate (one pass) + bias + log_softmax -----
__global__ __launch_bounds__(256) void agg2_kernel(
    const float* __restrict__ b2, float* __restrict__ out)
{
    const int n = (blockIdx.x * 256 + threadIdx.x) >> 5;
    const int l = threadIdx.x & 31;
    const int beg = g_off[n], end = g_off[n + 1];
    const float ad2n = g_ad2[n];
    const bool act = l < 10;

    float den = 0.f;
    float4 acc = make_float4(0.f, 0.f, 0.f, 0.f);

    for (int base = beg; base < end; base += 32) {
        const int je = min(32, end - base);
        const int sj = (l < je) ? __ldg(&g_ssrc[base + l]) : 0;
        int k = 0;
        #pragma unroll 1
        for (; k + 4 <= je; k += 4) {
            int s0 = __shfl_sync(FULL, sj, k);
            int s1 = __shfl_sync(FULL, sj, k + 1);
            int s2 = __shfl_sync(FULL, sj, k + 2);
            int s3 = __shfl_sync(FULL, sj, k + 3);
            float e0 = leaky_exp(__ldg(&g_as2[s0]) + ad2n);
            float e1 = leaky_exp(__ldg(&g_as2[s1]) + ad2n);
            float e2 = leaky_exp(__ldg(&g_as2[s2]) + ad2n);
            float e3 = leaky_exp(__ldg(&g_as2[s3]) + ad2n);
            den += (e0 + e1) + (e2 + e3);
            if (act) {
                fma4(acc, e0, g_g2[s0 * 10 + l]);
                fma4(acc, e1, g_g2[s1 * 10 + l]);
                fma4(acc, e2, g_g2[s2 * 10 + l]);
                fma4(acc, e3, g_g2[s3 * 10 + l]);
            }
        }
        for (; k < je; k++) {
            int s = __shfl_sync(FULL, sj, k);
            float e = leaky_exp(__ldg(&g_as2[s]) + ad2n);
            den += e;
            if (act) fma4(acc, e, g_g2[s * 10 + l]);
        }
    }
    const float rinv = 1.f / (den + EPSV);

    float4 v = make_float4(-1e30f, -1e30f, -1e30f, -1e30f);
    if (act) {
        v = ((const float4*)b2)[l];
        v.x += acc.x * rinv; v.y += acc.y * rinv;
        v.z += acc.z * rinv; v.w += acc.w * rinv;
    }
    float mx = act ? fmaxf(fmaxf(v.x, v.y), fmaxf(v.z, v.w)) : -1e30f;
    #pragma unroll
    for (int o = 16; o; o >>= 1) mx = fmaxf(mx, __shfl_xor_sync(FULL, mx, o));
    float sm = 0.f;
    if (act) sm = __expf(v.x - mx) + __expf(v.y - mx) + __expf(v.z - mx) + __expf(v.w - mx);
    #pragma unroll
    for (int o = 16; o; o >>= 1) sm += __shfl_xor_sync(FULL, sm, o);
    float lse = mx + logf(sm);
    if (act)
        ((float4*)out)[n * 10 + l] =
            make_float4(v.x - lse, v.y - lse, v.z - lse, v.w - lse);
}

// ---------------- launch ----------------
extern "C" void kernel_launch(void* const* d_in, const int* in_sizes, int n_in,
                              void* d_out, int out_size)
{
    const float* x      = (const float*)d_in[0];
    const int*   eidx   = (const int*)d_in[1];
    const float* W1     = (const float*)d_in[2];
    const float* a_src1 = (const float*)d_in[3];
    const float* a_dst1 = (const float*)d_in[4];
    const float* b1     = (const float*)d_in[5];
    const float* W2     = (const float*)d_in[6];
    const float* a_src2 = (const float*)d_in[7];
    const float* a_dst2 = (const float*)d_in[8];
    const float* b2     = (const float*)d_in[9];
    const int* src = eidx;
    const int* dst = eidx + EE;
    float* out = (float*)d_out;

    const int G1_SMEM = (128 * 128 + 64 * 128) * 4;   // 96 KB
    (void)cudaFuncSetAttribute(gemm1_kernel,
                               cudaFuncAttributeMaxDynamicSharedMemorySize, G1_SMEM);

    zero_kernel<<<(NN + 255) / 256, 256>>>();                      // 1
    hist_kernel<<<EE / 256, 256>>>(dst);                           // 2
    scan1_kernel<<<98, 1024>>>();                                  // 3
    gemm1_kernel<<<(NN + 63) / 64, 256, G1_SMEM>>>(x, W1, a_src1, a_dst1); // 4 (ncu)
    scanB_kernel<<<98, 1024>>>();                                  // 5
    scatter_kernel<<<EE / 256, 256>>>(src, dst);                   // 6
    agg1_kernel<<<NN / 8, 256>>>(b1);                              // 7
    gemm2_kernel<<<(NN + 255) / 256, 256>>>(W2, a_src2, a_dst2);   // 8
    agg2_kernel<<<NN / 8, 256>>>(b2, out);                         // 9
}